// round 5
// baseline (speedup 1.0000x reference)
#include <cuda_runtime.h>

#define FULLMASK 0xffffffffu

constexpr int Bsz  = 4096;
constexpr int Ln   = 50;
constexpr int Dm   = 64;
constexpr int ROWS = Bsz * Ln;   // 204800

// ---------------- scratch ---------------------------------------------------
__device__ float g_fjt[ROWS * Dm];     // [B*L, 64]
__device__ float g_scores[ROWS];       // [B*L]

// ---------------- helpers ---------------------------------------------------
__device__ __forceinline__ float wredmax(float v) {
#pragma unroll
    for (int o = 16; o; o >>= 1) v = fmaxf(v, __shfl_xor_sync(FULLMASK, v, o));
    return v;
}
__device__ __forceinline__ float wredsum(float v) {
#pragma unroll
    for (int o = 16; o; o >>= 1) v += __shfl_xor_sync(FULLMASK, v, o);
    return v;
}
__device__ __forceinline__ void cpf(float* dst, const float* __restrict__ src, int n) {
    for (int i = threadIdx.x; i < n; i += blockDim.x) dst[i] = src[i];
}
// Pair columns j and j+32 of a [K x 64] row-major weight matrix into float2.
__device__ __forceinline__ void cpf_pair(float2* dst, const float* __restrict__ W, int K) {
    for (int i = threadIdx.x; i < K * 32; i += blockDim.x) {
        int k = i >> 5, j = i & 31;
        dst[i] = make_float2(W[k * 64 + j], W[k * 64 + j + 32]);
    }
}

__device__ __forceinline__ unsigned long long ld_u64(const float2* p) {
    return *reinterpret_cast<const unsigned long long*>(p);
}
__device__ __forceinline__ void ffma2(unsigned long long& d, unsigned long long a,
                                      unsigned long long b) {
    asm("fma.rn.f32x2 %0, %1, %2, %0;" : "+l"(d) : "l"(a), "l"(b));
}
__device__ __forceinline__ float2 unpack2(unsigned long long a) {
    float2 v;
    asm("mov.b64 {%0, %1}, %2;" : "=f"(v.x), "=f"(v.y) : "l"(a));
    return v;
}

// 4-row x 2-col packed MLP layer. xin: duplicated activations, layout
// xin[r*XS + k] = {x_rk, x_rk}. Wp: paired weights [K][32]. Result (post-bias,
// optional relu) returned in o[r] = {out_col_j, out_col_j32}.
template <int K, int XS, bool RELU>
__device__ __forceinline__ void mlp4p(const float2* __restrict__ Wp,
                                      const float2* __restrict__ bp,
                                      const float2* __restrict__ xin,
                                      int j, float2 o[4]) {
    unsigned long long a0 = 0, a1 = 0, a2 = 0, a3 = 0;
#pragma unroll 8
    for (int k = 0; k < K; k++) {
        unsigned long long w  = ld_u64(Wp + (k << 5) + j);
        unsigned long long x0 = ld_u64(xin + k);
        unsigned long long x1 = ld_u64(xin + XS + k);
        unsigned long long x2 = ld_u64(xin + 2 * XS + k);
        unsigned long long x3 = ld_u64(xin + 3 * XS + k);
        ffma2(a0, x0, w); ffma2(a1, x1, w);
        ffma2(a2, x2, w); ffma2(a3, x3, w);
    }
    float2 b = bp[j];
    unsigned long long aa[4] = {a0, a1, a2, a3};
#pragma unroll
    for (int r = 0; r < 4; r++) {
        float2 v = unpack2(aa[r]);
        v.x += b.x; v.y += b.y;
        if (RELU) { v.x = fmaxf(v.x, 0.f); v.y = fmaxf(v.y, 0.f); }
        o[r] = v;
    }
}

// store duplicated outputs into next-layer activation buffer
template <int XS>
__device__ __forceinline__ void st_dup(float2* __restrict__ buf, int j,
                                       const float2 o[4]) {
#pragma unroll
    for (int r = 0; r < 4; r++) {
        buf[r * XS + j]      = make_float2(o[r].x, o[r].x);
        buf[r * XS + j + 32] = make_float2(o[r].y, o[r].y);
    }
}

// ---------------- K1 smem layout (float2 units) -----------------------------
constexpr int P_GV1  = 0;          // 4096
constexpr int P_GV2  = 4096;       // 2048
constexpr int P_GV3  = 6144;       // 2048
constexpr int P_AT1  = 8192;       // 4096
constexpr int P_AT2  = 12288;      // 2048
constexpr int PB_GV1 = 14336;      // 32 each
constexpr int PB_GV2 = 14368;
constexpr int PB_GV3 = 14400;
constexpr int PB_AT1 = 14432;
constexpr int PB_AT2 = 14464;
constexpr int P_AT3  = 14496;      // 32 (paired att_w3)
constexpr int P_AT3B = 14528;      // 1 (bias in .x)
constexpr int P_BUF  = 14530;      // per-warp: A 4*132=528, B 4*68=272 -> 800
constexpr int XS_A   = 132;
constexpr int XS_B   = 68;
constexpr int WBUF   = 800;
constexpr int SMEM1_F2 = P_BUF + 16 * WBUF;   // 27330 f2 = 218640 B

__global__ __launch_bounds__(512, 1)
void k_rows(const int* __restrict__ nodes_v, const int* __restrict__ neigh_u,
            const int* __restrict__ neigh_r,
            const float* __restrict__ embed_u, const float* __restrict__ embed_i,
            const float* __restrict__ embed_r,
            const float* __restrict__ gw1, const float* __restrict__ gb1,
            const float* __restrict__ gw2, const float* __restrict__ gb2,
            const float* __restrict__ gw3, const float* __restrict__ gb3,
            const float* __restrict__ aw1, const float* __restrict__ ab1,
            const float* __restrict__ aw2, const float* __restrict__ ab2,
            const float* __restrict__ aw3, const float* __restrict__ ab3) {
    extern __shared__ float2 sm[];
    cpf_pair(sm + P_GV1, gw1, 128);
    cpf_pair(sm + P_GV2, gw2, 64);
    cpf_pair(sm + P_GV3, gw3, 64);
    cpf_pair(sm + P_AT1, aw1, 128);
    cpf_pair(sm + P_AT2, aw2, 64);
    cpf_pair(sm + PB_GV1, gb1, 1);
    cpf_pair(sm + PB_GV2, gb2, 1);
    cpf_pair(sm + PB_GV3, gb3, 1);
    cpf_pair(sm + PB_AT1, ab1, 1);
    cpf_pair(sm + PB_AT2, ab2, 1);
    cpf_pair(sm + P_AT3, aw3, 1);
    if (threadIdx.x == 0) sm[P_AT3B] = make_float2(ab3[0], 0.f);
    __syncthreads();

    const int wid  = threadIdx.x >> 5;
    const int lane = threadIdx.x & 31;
    float2* A = sm + P_BUF + wid * WBUF;       // 4 x XS_A
    float2* B = A + 4 * XS_A;                  // 4 x XS_B

    const float2 w3p = sm[P_AT3 + lane];
    const float  b3  = sm[P_AT3B].x;

    const int NTILES = ROWS / 64;   // 3200
    for (int tile = blockIdx.x; tile < NTILES; tile += gridDim.x) {
        const int row0 = tile * 64 + wid * 4;
        int ivr[4];
        // gather x = [pt | er] duplicated
#pragma unroll
        for (int r = 0; r < 4; r++) {
            int row = row0 + r;
            int b   = row / Ln;
            int u   = neigh_u[row];
            int rr  = neigh_r[row];
            ivr[r]  = nodes_v[b];
            float2 pu = ((const float2*)embed_u)[u  * 32 + lane];
            float2 pe = ((const float2*)embed_r)[rr * 32 + lane];
            A[r * XS_A + 2 * lane]          = make_float2(pu.x, pu.x);
            A[r * XS_A + 2 * lane + 1]      = make_float2(pu.y, pu.y);
            A[r * XS_A + 64 + 2 * lane]     = make_float2(pe.x, pe.x);
            A[r * XS_A + 64 + 2 * lane + 1] = make_float2(pe.y, pe.y);
        }
        __syncwarp();

        float2 o[4];
        mlp4p<128, XS_A, true>(sm + P_GV1, sm + PB_GV1, A, lane, o);
        st_dup<XS_B>(B, lane, o);
        __syncwarp();
        mlp4p<64, XS_B, true>(sm + P_GV2, sm + PB_GV2, B, lane, o);
        __syncwarp();
        st_dup<XS_A>(A, lane, o);
        __syncwarp();
        mlp4p<64, XS_A, false>(sm + P_GV3, sm + PB_GV3, A, lane, o);
        __syncwarp();

        // fjt -> global, and rebuild A = [fjt | qj] duplicated
#pragma unroll
        for (int r = 0; r < 4; r++) {
            int row = row0 + r;
            g_fjt[row * Dm + lane]      = o[r].x;
            g_fjt[row * Dm + lane + 32] = o[r].y;
            float2 q = ((const float2*)embed_i)[ivr[r] * 32 + lane];
            A[r * XS_A + 64 + 2 * lane]     = make_float2(q.x, q.x);
            A[r * XS_A + 64 + 2 * lane + 1] = make_float2(q.y, q.y);
        }
        st_dup<XS_A>(A, lane, o);
        __syncwarp();

        mlp4p<128, XS_A, true>(sm + P_AT1, sm + PB_AT1, A, lane, o);
        st_dup<XS_B>(B, lane, o);
        __syncwarp();
        mlp4p<64, XS_B, true>(sm + P_AT2, sm + PB_AT2, B, lane, o);

#pragma unroll
        for (int r = 0; r < 4; r++) {
            float s = o[r].x * w3p.x + o[r].y * w3p.y;
            s = wredsum(s);
            if (lane == 0) g_scores[row0 + r] = s + b3;
        }
        __syncwarp();
    }
}

// ---------------- K2: softmax + aggregation + combine MLP -------------------
constexpr int OFF_W1  = 0;         // 8192
constexpr int OFF_W2  = 8192;      // 4096
constexpr int OFF_B1  = 12288;     // 64
constexpr int OFF_B2  = 12352;     // 64
constexpr int OFF_XB2 = 12416;     // 8 warps * 128
constexpr int OFF_MU  = 12416 + 8 * 128;   // 8 warps * 64
constexpr int SMEM2_FLOATS = OFF_MU + 8 * 64;

template <int K, bool RELU>
__device__ __forceinline__ void mlp1(const float* __restrict__ W,
                                     const float* __restrict__ bias,
                                     const float* __restrict__ xb, int lane,
                                     float& o0, float& o1) {
    float c0 = 0.f, c1 = 0.f;
#pragma unroll 8
    for (int k = 0; k < K; k++) {
        float x = xb[k];
        c0 = fmaf(x, W[k * Dm + lane], c0);
        c1 = fmaf(x, W[k * Dm + lane + 32], c1);
    }
    c0 += bias[lane]; c1 += bias[lane + 32];
    if (RELU) { c0 = fmaxf(c0, 0.f); c1 = fmaxf(c1, 0.f); }
    o0 = c0; o1 = c1;
}

__global__ __launch_bounds__(256, 1)
void k_agg(const int* __restrict__ nodes_v, const float* __restrict__ embed_i,
           const float* __restrict__ w1, const float* __restrict__ b1,
           const float* __restrict__ w2, const float* __restrict__ b2,
           float* __restrict__ out) {
    extern __shared__ float smf[];
    cpf(smf + OFF_W1, w1, 8192);
    cpf(smf + OFF_W2, w2, 4096);
    cpf(smf + OFF_B1, b1, 64);
    cpf(smf + OFF_B2, b2, 64);
    __syncthreads();

    const int wid  = threadIdx.x >> 5;
    const int lane = threadIdx.x & 31;
    const int nw   = blockDim.x >> 5;
    float* xb = smf + OFF_XB2 + wid * 128;
    float* mu = smf + OFF_MU  + wid * 64;

    for (int b = blockIdx.x * nw + wid; b < Bsz; b += gridDim.x * nw) {
        const float* sc = g_scores + b * Ln;
        float s0 = (lane < Ln)        ? sc[lane]      : -1e30f;
        float s1 = ((lane + 32) < Ln) ? sc[lane + 32] : -1e30f;
        float m  = wredmax(fmaxf(s0, s1));
        float e0 = (lane < Ln)        ? expf(s0 - m) : 0.f;
        float e1 = ((lane + 32) < Ln) ? expf(s1 - m) : 0.f;
        float inv = 1.f / wredsum(e0 + e1);
        mu[lane]      = e0 * inv;
        mu[lane + 32] = e1 * inv;
        __syncwarp();

        float a0 = 0.f, a1 = 0.f;
        const float* fj = g_fjt + (long)b * Ln * Dm;
#pragma unroll 2
        for (int l = 0; l < Ln; l++) {
            float mm = mu[l];
            a0 = fmaf(mm, fj[l * Dm + lane], a0);
            a1 = fmaf(mm, fj[l * Dm + lane + 32], a1);
        }
        xb[lane]      = a0;
        xb[lane + 32] = a1;
        int iv = nodes_v[b];
        ((float2*)(xb + 64))[lane] = ((const float2*)embed_i)[iv * 32 + lane];
        __syncwarp();

        float z0, z1;
        mlp1<128, true>(smf + OFF_W1, smf + OFF_B1, xb, lane, z0, z1);
        __syncwarp();
        xb[lane]      = z0;
        xb[lane + 32] = z1;
        __syncwarp();
        float o0, o1;
        mlp1<64, true>(smf + OFF_W2, smf + OFF_B2, xb, lane, o0, o1);
        out[b * Dm + lane]      = o0;
        out[b * Dm + lane + 32] = o1;
        __syncwarp();
    }
}

// ---------------- launch ----------------------------------------------------
extern "C" void kernel_launch(void* const* d_in, const int* in_sizes, int n_in,
                              void* d_out, int out_size) {
    const int*   nodes_v = (const int*)d_in[0];
    const int*   neigh_u = (const int*)d_in[1];
    const int*   neigh_r = (const int*)d_in[2];
    const float* embed_u = (const float*)d_in[3];
    const float* embed_i = (const float*)d_in[4];
    const float* embed_r = (const float*)d_in[5];
    const float* gv_w1 = (const float*)d_in[6];
    const float* gv_b1 = (const float*)d_in[7];
    const float* gv_w2 = (const float*)d_in[8];
    const float* gv_b2 = (const float*)d_in[9];
    const float* gv_w3 = (const float*)d_in[10];
    const float* gv_b3 = (const float*)d_in[11];
    const float* at_w1 = (const float*)d_in[12];
    const float* at_b1 = (const float*)d_in[13];
    const float* at_w2 = (const float*)d_in[14];
    const float* at_b2 = (const float*)d_in[15];
    const float* at_w3 = (const float*)d_in[16];
    const float* at_b3 = (const float*)d_in[17];
    const float* wr1_w = (const float*)d_in[18];
    const float* wr1_b = (const float*)d_in[19];
    const float* wr2_w = (const float*)d_in[20];
    const float* wr2_b = (const float*)d_in[21];
    float* out = (float*)d_out;

    int nsm = 148;
    cudaDeviceGetAttribute(&nsm, cudaDevAttrMultiProcessorCount, 0);

    const size_t s1 = SMEM1_F2 * sizeof(float2);
    const size_t s2 = SMEM2_FLOATS * sizeof(float);
    cudaFuncSetAttribute(k_rows, cudaFuncAttributeMaxDynamicSharedMemorySize, (int)s1);
    cudaFuncSetAttribute(k_agg,  cudaFuncAttributeMaxDynamicSharedMemorySize, (int)s2);

    k_rows<<<nsm, 512, s1>>>(nodes_v, neigh_u, neigh_r, embed_u, embed_i, embed_r,
                             gv_w1, gv_b1, gv_w2, gv_b2, gv_w3, gv_b3,
                             at_w1, at_b1, at_w2, at_b2, at_w3, at_b3);
    k_agg<<<512, 256, s2>>>(nodes_v, embed_i, wr1_w, wr1_b, wr2_w, wr2_b, out);
}

// round 6
// speedup vs baseline: 4.0759x; 4.0759x over previous
#include <cuda_runtime.h>
#include <cstdint>

#define FULLMASK 0xffffffffu

constexpr int Bsz  = 4096;
constexpr int Ln   = 50;
constexpr int Dm   = 64;
constexpr int ROWS = Bsz * Ln;       // 204800
constexpr int NTIL = ROWS / 16;      // 12800 16-row tiles
constexpr int SK   = 136;            // X row stride (floats), 2-way-conflict pad
constexpr int WARPS = 12;

// ---------------- scratch ---------------------------------------------------
__device__ float g_fjt[ROWS * Dm];
__device__ float g_scores[ROWS];

// ---------------- smem float offsets (k_rows) -------------------------------
// WF: 7168 uint4 (gv1 2048 | gv2 1024 | gv3 1024 | at1 2048 | at2 1024)
constexpr int F_WF  = 0;                 // 28672 floats
constexpr int F_B1  = 28672;
constexpr int F_B2  = 28736;
constexpr int F_B3  = 28800;
constexpr int F_BA1 = 28864;
constexpr int F_BA2 = 28928;
constexpr int F_W3  = 28992;
constexpr int F_B3S = 29056;
constexpr int F_X   = 29060;
constexpr int SMEM1_FLOATS = F_X + WARPS * 16 * SK;   // 55172 floats = 220688 B
constexpr int U_GV1 = 0, U_GV2 = 2048, U_GV3 = 3072, U_AT1 = 4096, U_AT2 = 6144;

// ---------------- helpers ---------------------------------------------------
__device__ __forceinline__ void cpf(float* dst, const float* __restrict__ src, int n) {
    for (int i = threadIdx.x; i < n; i += blockDim.x) dst[i] = src[i];
}
// pack {lo: bf16(x0), hi: bf16(x1)}
__device__ __forceinline__ uint32_t bfpack(float x0, float x1) {
    uint32_t r;
    asm("cvt.rn.bf16x2.f32 %0, %1, %2;" : "=r"(r) : "f"(x1), "f"(x0));
    return r;
}
// split (x0,x1) -> hi-pack + lo-pack (bf16 pair each)
__device__ __forceinline__ void split2(float x0, float x1, uint32_t& hi, uint32_t& lo) {
    hi = bfpack(x0, x1);
    float h0 = __uint_as_float(hi << 16);
    float h1 = __uint_as_float(hi & 0xffff0000u);
    lo = bfpack(x0 - h0, x1 - h1);
}
__device__ __forceinline__ void mma16816(float4& c, const uint32_t a[4],
                                         uint32_t b0, uint32_t b1) {
    asm volatile(
        "mma.sync.aligned.m16n8k16.row.col.f32.bf16.bf16.f32 "
        "{%0,%1,%2,%3}, {%4,%5,%6,%7}, {%8,%9}, {%0,%1,%2,%3};\n"
        : "+f"(c.x), "+f"(c.y), "+f"(c.z), "+f"(c.w)
        : "r"(a[0]), "r"(a[1]), "r"(a[2]), "r"(a[3]), "r"(b0), "r"(b1));
}
__device__ __forceinline__ void mma3(float4& c, const uint32_t ah[4],
                                     const uint32_t al[4], uint4 w) {
    mma16816(c, ah, w.x, w.y);   // Ahi * Bhi
    mma16816(c, ah, w.z, w.w);   // Ahi * Blo
    mma16816(c, al, w.x, w.y);   // Alo * Bhi
}

// Pre-split weights [K x 64] into B-fragment order: entry (kk, nn, lane) =
// {bhi0, bhi1, blo0, blo1}; b0 covers k = kk*16 + t2, t2+1; b1 k +8,+9; col nn*8+g.
__device__ void stage_w(uint4* dst, const float* __restrict__ W, int KSTEPS) {
    int total = KSTEPS * 256;
    for (int i = threadIdx.x; i < total; i += blockDim.x) {
        int kk = i >> 8, rem = i & 255, nn = rem >> 5, lane = rem & 31;
        int g = lane >> 2, t2 = (lane & 3) * 2;
        int col = nn * 8 + g;
        int k0 = kk * 16 + t2;
        float w00 = W[k0 * 64 + col];
        float w01 = W[(k0 + 1) * 64 + col];
        float w08 = W[(k0 + 8) * 64 + col];
        float w09 = W[(k0 + 9) * 64 + col];
        uint4 e;
        uint32_t lo;
        split2(w00, w01, e.x, lo); e.z = lo;
        split2(w08, w09, e.y, lo); e.w = lo;
        dst[i] = e;
    }
}

__device__ __forceinline__ void bias_act(float4 C[8], const float2* __restrict__ b2,
                                         int lane, bool relu) {
    int t = lane & 3;
#pragma unroll
    for (int nn = 0; nn < 8; nn++) {
        float2 b = b2[nn * 4 + t];
        C[nn].x += b.x; C[nn].y += b.y; C[nn].z += b.x; C[nn].w += b.y;
        if (relu) {
            C[nn].x = fmaxf(C[nn].x, 0.f); C[nn].y = fmaxf(C[nn].y, 0.f);
            C[nn].z = fmaxf(C[nn].z, 0.f); C[nn].w = fmaxf(C[nn].w, 0.f);
        }
    }
}

// one k-step (16 cols starting at col c0) of A from smem X
__device__ __forceinline__ void afrag_fromX(const float* __restrict__ Xw, int g,
                                            int t2, int c0, uint32_t ah[4],
                                            uint32_t al[4]) {
    const float* rA = Xw + g * SK + c0 + t2;
    const float* rB = Xw + (g + 8) * SK + c0 + t2;
    float2 p0 = *(const float2*)(rA);
    float2 p1 = *(const float2*)(rB);
    float2 p2 = *(const float2*)(rA + 8);
    float2 p3 = *(const float2*)(rB + 8);
    split2(p0.x, p0.y, ah[0], al[0]);
    split2(p1.x, p1.y, ah[1], al[1]);
    split2(p2.x, p2.y, ah[2], al[2]);
    split2(p3.x, p3.y, ah[3], al[3]);
}
// one k-step of A from previous-layer C fragments (cols 16kk.. = nn pair 2kk,2kk+1)
__device__ __forceinline__ void afrag_fromC(const float4& u, const float4& v,
                                            uint32_t ah[4], uint32_t al[4]) {
    split2(u.x, u.y, ah[0], al[0]);   // (g,   2t..)
    split2(u.z, u.w, ah[1], al[1]);   // (g+8, 2t..)
    split2(v.x, v.y, ah[2], al[2]);   // (g,   2t+8..)
    split2(v.z, v.w, ah[3], al[3]);   // (g+8, 2t+8..)
}

template <int KSTEPS>
__device__ __forceinline__ void gemm_fromX(const float* __restrict__ Xw,
                                           const uint4* __restrict__ WF,
                                           int g, int t2, int lane, float4 C[8]) {
#pragma unroll
    for (int kk = 0; kk < KSTEPS; kk++) {
        uint32_t ah[4], al[4];
        afrag_fromX(Xw, g, t2, kk * 16, ah, al);
        const uint4* wk = WF + kk * 256 + lane;
#pragma unroll
        for (int nn = 0; nn < 8; nn++) mma3(C[nn], ah, al, wk[nn * 32]);
    }
}
__device__ __forceinline__ void gemm_fromC(const float4 P[8],
                                           const uint4* __restrict__ WF,
                                           int lane, float4 C[8]) {
#pragma unroll
    for (int kk = 0; kk < 4; kk++) {
        uint32_t ah[4], al[4];
        afrag_fromC(P[2 * kk], P[2 * kk + 1], ah, al);
        const uint4* wk = WF + kk * 256 + lane;
#pragma unroll
        for (int nn = 0; nn < 8; nn++) mma3(C[nn], ah, al, wk[nn * 32]);
    }
}

// ---------------- K1: fused row MLPs on tensor cores ------------------------
__global__ __launch_bounds__(32 * WARPS, 1)
void k_rows(const int* __restrict__ nodes_v, const int* __restrict__ neigh_u,
            const int* __restrict__ neigh_r,
            const float* __restrict__ embed_u, const float* __restrict__ embed_i,
            const float* __restrict__ embed_r,
            const float* __restrict__ gw1, const float* __restrict__ gb1,
            const float* __restrict__ gw2, const float* __restrict__ gb2,
            const float* __restrict__ gw3, const float* __restrict__ gb3,
            const float* __restrict__ aw1, const float* __restrict__ ab1,
            const float* __restrict__ aw2, const float* __restrict__ ab2,
            const float* __restrict__ aw3, const float* __restrict__ ab3) {
    extern __shared__ float sm[];
    uint4* WF = reinterpret_cast<uint4*>(sm + F_WF);
    stage_w(WF + U_GV1, gw1, 8);
    stage_w(WF + U_GV2, gw2, 4);
    stage_w(WF + U_GV3, gw3, 4);
    stage_w(WF + U_AT1, aw1, 8);
    stage_w(WF + U_AT2, aw2, 4);
    cpf(sm + F_B1,  gb1, 64);
    cpf(sm + F_B2,  gb2, 64);
    cpf(sm + F_B3,  gb3, 64);
    cpf(sm + F_BA1, ab1, 64);
    cpf(sm + F_BA2, ab2, 64);
    cpf(sm + F_W3,  aw3, 64);
    if (threadIdx.x == 0) sm[F_B3S] = ab3[0];
    __syncthreads();

    const int wid  = threadIdx.x >> 5;
    const int lane = threadIdx.x & 31;
    const int g    = lane >> 2;
    const int t2   = (lane & 3) * 2;
    float* Xw = sm + F_X + wid * (16 * SK);
    const float b3 = sm[F_B3S];

    const int wg      = blockIdx.x * WARPS + wid;
    const int wstride = gridDim.x * WARPS;

    for (int tile = wg; tile < NTIL; tile += wstride) {
        const int row0 = tile * 16;
        // ---- stage X = [pt | er] for 16 rows
#pragma unroll 4
        for (int r = 0; r < 16; r++) {
            int row = row0 + r;
            int u   = neigh_u[row];
            int rr  = neigh_r[row];
            float2 pu = ((const float2*)embed_u)[u  * 32 + lane];
            float2 pe = ((const float2*)embed_r)[rr * 32 + lane];
            *(float2*)(Xw + r * SK + 2 * lane)      = pu;
            *(float2*)(Xw + r * SK + 64 + 2 * lane) = pe;
        }
        __syncwarp();

        float4 C[8] = {};
        gemm_fromX<8>(Xw, WF + U_GV1, g, t2, lane, C);
        bias_act(C, (const float2*)(sm + F_B1), lane, true);

        float4 D[8] = {};
        gemm_fromC(C, WF + U_GV2, lane, D);
        bias_act(D, (const float2*)(sm + F_B2), lane, true);

#pragma unroll
        for (int nn = 0; nn < 8; nn++) C[nn] = make_float4(0.f, 0.f, 0.f, 0.f);
        gemm_fromC(D, WF + U_GV3, lane, C);
        bias_act(C, (const float2*)(sm + F_B3), lane, false);   // C = fjt frags

        // ---- fjt -> global; stage qj into X[.,64..127]
#pragma unroll
        for (int nn = 0; nn < 8; nn++) {
            float* p0 = g_fjt + (row0 + g) * Dm + nn * 8 + t2;
            float* p1 = g_fjt + (row0 + g + 8) * Dm + nn * 8 + t2;
            *(float2*)p0 = make_float2(C[nn].x, C[nn].y);
            *(float2*)p1 = make_float2(C[nn].z, C[nn].w);
        }
#pragma unroll 4
        for (int r = 0; r < 16; r++) {
            int iv = nodes_v[(row0 + r) / Ln];
            float2 q = ((const float2*)embed_i)[iv * 32 + lane];
            *(float2*)(Xw + r * SK + 64 + 2 * lane) = q;
        }
        __syncwarp();

        // ---- at1: k 0..63 from fjt frags (C), k 64..127 from X
#pragma unroll
        for (int nn = 0; nn < 8; nn++) D[nn] = make_float4(0.f, 0.f, 0.f, 0.f);
#pragma unroll
        for (int kk = 0; kk < 4; kk++) {
            uint32_t ah[4], al[4];
            afrag_fromC(C[2 * kk], C[2 * kk + 1], ah, al);
            const uint4* wk = WF + U_AT1 + kk * 256 + lane;
#pragma unroll
            for (int nn = 0; nn < 8; nn++) mma3(D[nn], ah, al, wk[nn * 32]);
        }
#pragma unroll
        for (int kk = 4; kk < 8; kk++) {
            uint32_t ah[4], al[4];
            afrag_fromX(Xw, g, t2, kk * 16, ah, al);
            const uint4* wk = WF + U_AT1 + kk * 256 + lane;
#pragma unroll
            for (int nn = 0; nn < 8; nn++) mma3(D[nn], ah, al, wk[nn * 32]);
        }
        bias_act(D, (const float2*)(sm + F_BA1), lane, true);

#pragma unroll
        for (int nn = 0; nn < 8; nn++) C[nn] = make_float4(0.f, 0.f, 0.f, 0.f);
        gemm_fromC(D, WF + U_AT2, lane, C);
        bias_act(C, (const float2*)(sm + F_BA2), lane, true);

        // ---- scores: dot with att_w3 + reduce over 4 lanes of group
        float s0 = 0.f, s1 = 0.f;
        const float2* w32 = (const float2*)(sm + F_W3);
#pragma unroll
        for (int nn = 0; nn < 8; nn++) {
            float2 w = w32[nn * 4 + (lane & 3)];
            s0 += C[nn].x * w.x + C[nn].y * w.y;
            s1 += C[nn].z * w.x + C[nn].w * w.y;
        }
        s0 += __shfl_xor_sync(FULLMASK, s0, 1);
        s0 += __shfl_xor_sync(FULLMASK, s0, 2);
        s1 += __shfl_xor_sync(FULLMASK, s1, 1);
        s1 += __shfl_xor_sync(FULLMASK, s1, 2);
        if ((lane & 3) == 0) {
            g_scores[row0 + g]     = s0 + b3;
            g_scores[row0 + g + 8] = s1 + b3;
        }
        __syncwarp();
    }
}

// ---------------- K2: softmax + aggregation + combine MLP -------------------
__device__ __forceinline__ float wredmax(float v) {
#pragma unroll
    for (int o = 16; o; o >>= 1) v = fmaxf(v, __shfl_xor_sync(FULLMASK, v, o));
    return v;
}
__device__ __forceinline__ float wredsum(float v) {
#pragma unroll
    for (int o = 16; o; o >>= 1) v += __shfl_xor_sync(FULLMASK, v, o);
    return v;
}
constexpr int OFF_W1  = 0;
constexpr int OFF_W2  = 8192;
constexpr int OFF_B1  = 12288;
constexpr int OFF_B2  = 12352;
constexpr int OFF_XB2 = 12416;
constexpr int OFF_MU  = 12416 + 8 * 128;
constexpr int SMEM2_FLOATS = OFF_MU + 8 * 64;

template <int K, bool RELU>
__device__ __forceinline__ void mlp1(const float* __restrict__ W,
                                     const float* __restrict__ bias,
                                     const float* __restrict__ xb, int lane,
                                     float& o0, float& o1) {
    float c0 = 0.f, c1 = 0.f;
#pragma unroll 8
    for (int k = 0; k < K; k++) {
        float x = xb[k];
        c0 = fmaf(x, W[k * Dm + lane], c0);
        c1 = fmaf(x, W[k * Dm + lane + 32], c1);
    }
    c0 += bias[lane]; c1 += bias[lane + 32];
    if (RELU) { c0 = fmaxf(c0, 0.f); c1 = fmaxf(c1, 0.f); }
    o0 = c0; o1 = c1;
}

__global__ __launch_bounds__(256, 1)
void k_agg(const int* __restrict__ nodes_v, const float* __restrict__ embed_i,
           const float* __restrict__ w1, const float* __restrict__ b1,
           const float* __restrict__ w2, const float* __restrict__ b2,
           float* __restrict__ out) {
    extern __shared__ float smf[];
    cpf(smf + OFF_W1, w1, 8192);
    cpf(smf + OFF_W2, w2, 4096);
    cpf(smf + OFF_B1, b1, 64);
    cpf(smf + OFF_B2, b2, 64);
    __syncthreads();

    const int wid  = threadIdx.x >> 5;
    const int lane = threadIdx.x & 31;
    const int nw   = blockDim.x >> 5;
    float* xb = smf + OFF_XB2 + wid * 128;
    float* mu = smf + OFF_MU  + wid * 64;

    for (int b = blockIdx.x * nw + wid; b < Bsz; b += gridDim.x * nw) {
        const float* sc = g_scores + b * Ln;
        float s0 = (lane < Ln)        ? sc[lane]      : -1e30f;
        float s1 = ((lane + 32) < Ln) ? sc[lane + 32] : -1e30f;
        float m  = wredmax(fmaxf(s0, s1));
        float e0 = (lane < Ln)        ? expf(s0 - m) : 0.f;
        float e1 = ((lane + 32) < Ln) ? expf(s1 - m) : 0.f;
        float inv = 1.f / wredsum(e0 + e1);
        mu[lane]      = e0 * inv;
        mu[lane + 32] = e1 * inv;
        __syncwarp();

        float a0 = 0.f, a1 = 0.f;
        const float* fj = g_fjt + (long)b * Ln * Dm;
#pragma unroll 2
        for (int l = 0; l < Ln; l++) {
            float mm = mu[l];
            a0 = fmaf(mm, fj[l * Dm + lane], a0);
            a1 = fmaf(mm, fj[l * Dm + lane + 32], a1);
        }
        xb[lane]      = a0;
        xb[lane + 32] = a1;
        int iv = nodes_v[b];
        ((float2*)(xb + 64))[lane] = ((const float2*)embed_i)[iv * 32 + lane];
        __syncwarp();

        float z0, z1;
        mlp1<128, true>(smf + OFF_W1, smf + OFF_B1, xb, lane, z0, z1);
        __syncwarp();
        xb[lane]      = z0;
        xb[lane + 32] = z1;
        __syncwarp();
        float o0, o1;
        mlp1<64, true>(smf + OFF_W2, smf + OFF_B2, xb, lane, o0, o1);
        out[b * Dm + lane]      = o0;
        out[b * Dm + lane + 32] = o1;
        __syncwarp();
    }
}

// ---------------- launch ----------------------------------------------------
extern "C" void kernel_launch(void* const* d_in, const int* in_sizes, int n_in,
                              void* d_out, int out_size) {
    const int*   nodes_v = (const int*)d_in[0];
    const int*   neigh_u = (const int*)d_in[1];
    const int*   neigh_r = (const int*)d_in[2];
    const float* embed_u = (const float*)d_in[3];
    const float* embed_i = (const float*)d_in[4];
    const float* embed_r = (const float*)d_in[5];
    const float* gv_w1 = (const float*)d_in[6];
    const float* gv_b1 = (const float*)d_in[7];
    const float* gv_w2 = (const float*)d_in[8];
    const float* gv_b2 = (const float*)d_in[9];
    const float* gv_w3 = (const float*)d_in[10];
    const float* gv_b3 = (const float*)d_in[11];
    const float* at_w1 = (const float*)d_in[12];
    const float* at_b1 = (const float*)d_in[13];
    const float* at_w2 = (const float*)d_in[14];
    const float* at_b2 = (const float*)d_in[15];
    const float* at_w3 = (const float*)d_in[16];
    const float* at_b3 = (const float*)d_in[17];
    const float* wr1_w = (const float*)d_in[18];
    const float* wr1_b = (const float*)d_in[19];
    const float* wr2_w = (const float*)d_in[20];
    const float* wr2_b = (const float*)d_in[21];
    float* out = (float*)d_out;

    int nsm = 148;
    cudaDeviceGetAttribute(&nsm, cudaDevAttrMultiProcessorCount, 0);

    const size_t s1 = SMEM1_FLOATS * sizeof(float);   // 220688 B
    const size_t s2 = SMEM2_FLOATS * sizeof(float);
    cudaFuncSetAttribute(k_rows, cudaFuncAttributeMaxDynamicSharedMemorySize, (int)s1);
    cudaFuncSetAttribute(k_agg,  cudaFuncAttributeMaxDynamicSharedMemorySize, (int)s2);

    k_rows<<<nsm, 32 * WARPS, s1>>>(nodes_v, neigh_u, neigh_r,
                                    embed_u, embed_i, embed_r,
                                    gv_w1, gv_b1, gv_w2, gv_b2, gv_w3, gv_b3,
                                    at_w1, at_b1, at_w2, at_b2, at_w3, at_b3);
    k_agg<<<512, 256, s2>>>(nodes_v, embed_i, wr1_w, wr1_b, wr2_w, wr2_b, out);
}

// round 7
// speedup vs baseline: 4.2363x; 1.0393x over previous
#include <cuda_runtime.h>
#include <cstdint>

#define FULLMASK 0xffffffffu

constexpr int Bsz  = 4096;
constexpr int Ln   = 50;
constexpr int Dm   = 64;
constexpr int ROWS = Bsz * Ln;       // 204800
constexpr int NUNIT = ROWS / 32;     // 6400 32-row units
constexpr int WARPS = 12;

// ---------------- scratch ---------------------------------------------------
__device__ float g_fjt[ROWS * Dm];
__device__ float g_scores[ROWS];

// ---------------- smem float offsets (k_rows) -------------------------------
constexpr int F_WF  = 0;                  // 28672 floats (7168 uint4)
constexpr int F_ERT = 28672;              // 320 floats (80 uint4), 16B aligned
constexpr int F_B1  = 28992;
constexpr int F_B2  = 29056;
constexpr int F_B3  = 29120;
constexpr int F_BA1 = 29184;
constexpr int F_BA2 = 29248;
constexpr int F_W3  = 29312;
constexpr int F_B3S = 29376;
constexpr int SMEM1_FLOATS = 29380;       // ~117.5 KB
constexpr int U_GV1 = 0, U_GV2 = 2048, U_GV3 = 3072, U_AT1 = 4096, U_AT2 = 6144;

// ---------------- helpers ---------------------------------------------------
__device__ __forceinline__ void cpf(float* dst, const float* __restrict__ src, int n) {
    for (int i = threadIdx.x; i < n; i += blockDim.x) dst[i] = src[i];
}
__device__ __forceinline__ uint32_t bfpack(float x0, float x1) {
    uint32_t r;
    asm("cvt.rn.bf16x2.f32 %0, %1, %2;" : "=r"(r) : "f"(x1), "f"(x0));
    return r;
}
__device__ __forceinline__ void split2(float x0, float x1, uint32_t& hi, uint32_t& lo) {
    hi = bfpack(x0, x1);
    float h0 = __uint_as_float(hi << 16);
    float h1 = __uint_as_float(hi & 0xffff0000u);
    lo = bfpack(x0 - h0, x1 - h1);
}
__device__ __forceinline__ void mma16816(float4& c, const uint32_t a[4],
                                         uint32_t b0, uint32_t b1) {
    asm volatile(
        "mma.sync.aligned.m16n8k16.row.col.f32.bf16.bf16.f32 "
        "{%0,%1,%2,%3}, {%4,%5,%6,%7}, {%8,%9}, {%0,%1,%2,%3};\n"
        : "+f"(c.x), "+f"(c.y), "+f"(c.z), "+f"(c.w)
        : "r"(a[0]), "r"(a[1]), "r"(a[2]), "r"(a[3]), "r"(b0), "r"(b1));
}
__device__ __forceinline__ void mma3(float4& c, const uint32_t ah[4],
                                     const uint32_t al[4], uint4 w) {
    mma16816(c, ah, w.x, w.y);
    mma16816(c, ah, w.z, w.w);
    mma16816(c, al, w.x, w.y);
}

// weights [K x 64] -> B-fragment order {bhi0,bhi1,blo0,blo1}
__device__ void stage_w(uint4* dst, const float* __restrict__ W, int KSTEPS) {
    int total = KSTEPS * 256;
    for (int i = threadIdx.x; i < total; i += blockDim.x) {
        int kk = i >> 8, rem = i & 255, nn = rem >> 5, lane = rem & 31;
        int g = lane >> 2, t2 = (lane & 3) * 2;
        int col = nn * 8 + g;
        int k0 = kk * 16 + t2;
        uint4 e; uint32_t lo;
        split2(W[k0 * 64 + col], W[(k0 + 1) * 64 + col], e.x, lo); e.z = lo;
        split2(W[(k0 + 8) * 64 + col], W[(k0 + 9) * 64 + col], e.y, lo); e.w = lo;
        dst[i] = e;
    }
}

__device__ __forceinline__ void bias_act(float4 C[8], const float2* __restrict__ b2,
                                         int t, bool relu) {
#pragma unroll
    for (int nn = 0; nn < 8; nn++) {
        float2 b = b2[nn * 4 + t];
        C[nn].x += b.x; C[nn].y += b.y; C[nn].z += b.x; C[nn].w += b.y;
        if (relu) {
            C[nn].x = fmaxf(C[nn].x, 0.f); C[nn].y = fmaxf(C[nn].y, 0.f);
            C[nn].z = fmaxf(C[nn].z, 0.f); C[nn].w = fmaxf(C[nn].w, 0.f);
        }
    }
}

__device__ __forceinline__ void afrag_fromC(const float4& u, const float4& v,
                                            uint32_t ah[4], uint32_t al[4]) {
    split2(u.x, u.y, ah[0], al[0]);
    split2(u.z, u.w, ah[1], al[1]);
    split2(v.x, v.y, ah[2], al[2]);
    split2(v.z, v.w, ah[3], al[3]);
}

// dual-half fromC GEMM (K=64): both halves share each weight fragment read
__device__ __forceinline__ void gemm2_fromC(const float4 P0[8], const float4 P1[8],
                                            const uint4* __restrict__ WK, int lane,
                                            float4 C0[8], float4 C1[8]) {
#pragma unroll
    for (int kk = 0; kk < 4; kk++) {
        uint32_t ahA[4], alA[4], ahB[4], alB[4];
        afrag_fromC(P0[2 * kk], P0[2 * kk + 1], ahA, alA);
        afrag_fromC(P1[2 * kk], P1[2 * kk + 1], ahB, alB);
        const uint4* wk = WK + kk * 256 + lane;
#pragma unroll
        for (int nn = 0; nn < 8; nn++) {
            uint4 w = wk[nn * 32];
            mma3(C0[nn], ahA, alA, w);
            mma3(C1[nn], ahB, alB, w);
        }
    }
}

// ---------------- K1: fused row MLPs, M=32/warp, no X staging ---------------
__global__ __launch_bounds__(32 * WARPS, 1)
void k_rows(const int* __restrict__ nodes_v, const int* __restrict__ neigh_u,
            const int* __restrict__ neigh_r,
            const float* __restrict__ embed_u, const float* __restrict__ embed_i,
            const float* __restrict__ embed_r,
            const float* __restrict__ gw1, const float* __restrict__ gb1,
            const float* __restrict__ gw2, const float* __restrict__ gb2,
            const float* __restrict__ gw3, const float* __restrict__ gb3,
            const float* __restrict__ aw1, const float* __restrict__ ab1,
            const float* __restrict__ aw2, const float* __restrict__ ab2,
            const float* __restrict__ aw3, const float* __restrict__ ab3) {
    extern __shared__ float sm[];
    uint4* WF = reinterpret_cast<uint4*>(sm + F_WF);
    uint4* ERT = reinterpret_cast<uint4*>(sm + F_ERT);
    stage_w(WF + U_GV1, gw1, 8);
    stage_w(WF + U_GV2, gw2, 4);
    stage_w(WF + U_GV3, gw3, 4);
    stage_w(WF + U_AT1, aw1, 8);
    stage_w(WF + U_AT2, aw2, 4);
    // embed_r fragment LUT: [rr][kk][t] -> {hi01, lo01, hi89, lo89}
    for (int i = threadIdx.x; i < 80; i += blockDim.x) {
        int rr = i >> 4, kk = (i >> 2) & 3, t = i & 3;
        int c = kk * 16 + t * 2;
        const float* er = embed_r + rr * 64;
        uint4 e;
        split2(er[c], er[c + 1], e.x, e.y);
        split2(er[c + 8], er[c + 9], e.z, e.w);
        ERT[i] = e;
    }
    cpf(sm + F_B1,  gb1, 64);
    cpf(sm + F_B2,  gb2, 64);
    cpf(sm + F_B3,  gb3, 64);
    cpf(sm + F_BA1, ab1, 64);
    cpf(sm + F_BA2, ab2, 64);
    cpf(sm + F_W3,  aw3, 64);
    if (threadIdx.x == 0) sm[F_B3S] = ab3[0];
    __syncthreads();

    const int wid  = threadIdx.x >> 5;
    const int lane = threadIdx.x & 31;
    const int g    = lane >> 2;
    const int t    = lane & 3;
    const int t2   = t * 2;
    const float b3 = sm[F_B3S];

    const int wg      = blockIdx.x * WARPS + wid;
    const int wstride = gridDim.x * WARPS;

    for (int unit = wg; unit < NUNIT; unit += wstride) {
        const int row0 = unit * 32;
        // ---- indices for the 4 row-groups this lane touches
        int u0 = neigh_u[row0 + g],      u1 = neigh_u[row0 + 8 + g];
        int u2 = neigh_u[row0 + 16 + g], u3 = neigh_u[row0 + 24 + g];
        int r0i = neigh_r[row0 + g],      r1i = neigh_r[row0 + 8 + g];
        int r2i = neigh_r[row0 + 16 + g], r3i = neigh_r[row0 + 24 + g];
        const float* eu0 = embed_u + (size_t)u0 * 64;
        const float* eu1 = embed_u + (size_t)u1 * 64;
        const float* eu2 = embed_u + (size_t)u2 * 64;
        const float* eu3 = embed_u + (size_t)u3 * 64;

        // ---- prefetch pt operands (cols 0..63 of gv1)
        float2 PA0[4], PA1[4], PA2[4], PA3[4];
        float2 PB0[4], PB1[4], PB2[4], PB3[4];
#pragma unroll
        for (int kk = 0; kk < 4; kk++) {
            int c = kk * 16 + t2;
            PA0[kk] = *(const float2*)(eu0 + c);
            PA1[kk] = *(const float2*)(eu1 + c);
            PA2[kk] = *(const float2*)(eu0 + c + 8);
            PA3[kk] = *(const float2*)(eu1 + c + 8);
            PB0[kk] = *(const float2*)(eu2 + c);
            PB1[kk] = *(const float2*)(eu3 + c);
            PB2[kk] = *(const float2*)(eu2 + c + 8);
            PB3[kk] = *(const float2*)(eu3 + c + 8);
        }

        float4 C0[8] = {}, C1[8] = {};
        // ---- gv1, k-steps 0..3 (pt)
#pragma unroll
        for (int kk = 0; kk < 4; kk++) {
            uint32_t ahA[4], alA[4], ahB[4], alB[4];
            split2(PA0[kk].x, PA0[kk].y, ahA[0], alA[0]);
            split2(PA1[kk].x, PA1[kk].y, ahA[1], alA[1]);
            split2(PA2[kk].x, PA2[kk].y, ahA[2], alA[2]);
            split2(PA3[kk].x, PA3[kk].y, ahA[3], alA[3]);
            split2(PB0[kk].x, PB0[kk].y, ahB[0], alB[0]);
            split2(PB1[kk].x, PB1[kk].y, ahB[1], alB[1]);
            split2(PB2[kk].x, PB2[kk].y, ahB[2], alB[2]);
            split2(PB3[kk].x, PB3[kk].y, ahB[3], alB[3]);
            const uint4* wk = WF + U_GV1 + kk * 256 + lane;
#pragma unroll
            for (int nn = 0; nn < 8; nn++) {
                uint4 w = wk[nn * 32];
                mma3(C0[nn], ahA, alA, w);
                mma3(C1[nn], ahB, alB, w);
            }
        }
        // ---- gv1, k-steps 4..7 (er from LUT)
#pragma unroll
        for (int kk = 0; kk < 4; kk++) {
            uint32_t ahA[4], alA[4], ahB[4], alB[4];
            uint4 eA0 = ERT[(r0i * 4 + kk) * 4 + t];
            uint4 eA1 = ERT[(r1i * 4 + kk) * 4 + t];
            uint4 eB0 = ERT[(r2i * 4 + kk) * 4 + t];
            uint4 eB1 = ERT[(r3i * 4 + kk) * 4 + t];
            ahA[0] = eA0.x; alA[0] = eA0.y; ahA[2] = eA0.z; alA[2] = eA0.w;
            ahA[1] = eA1.x; alA[1] = eA1.y; ahA[3] = eA1.z; alA[3] = eA1.w;
            ahB[0] = eB0.x; alB[0] = eB0.y; ahB[2] = eB0.z; alB[2] = eB0.w;
            ahB[1] = eB1.x; alB[1] = eB1.y; ahB[3] = eB1.z; alB[3] = eB1.w;
            const uint4* wk = WF + U_GV1 + (kk + 4) * 256 + lane;
#pragma unroll
            for (int nn = 0; nn < 8; nn++) {
                uint4 w = wk[nn * 32];
                mma3(C0[nn], ahA, alA, w);
                mma3(C1[nn], ahB, alB, w);
            }
        }
        bias_act(C0, (const float2*)(sm + F_B1), t, true);
        bias_act(C1, (const float2*)(sm + F_B1), t, true);

        float4 D0[8] = {}, D1[8] = {};
        gemm2_fromC(C0, C1, WF + U_GV2, lane, D0, D1);
        bias_act(D0, (const float2*)(sm + F_B2), t, true);
        bias_act(D1, (const float2*)(sm + F_B2), t, true);

#pragma unroll
        for (int nn = 0; nn < 8; nn++) {
            C0[nn] = make_float4(0.f, 0.f, 0.f, 0.f);
            C1[nn] = make_float4(0.f, 0.f, 0.f, 0.f);
        }
        gemm2_fromC(D0, D1, WF + U_GV3, lane, C0, C1);
        bias_act(C0, (const float2*)(sm + F_B3), t, false);
        bias_act(C1, (const float2*)(sm + F_B3), t, false);   // C = fjt frags

        // ---- fjt -> global
#pragma unroll
        for (int nn = 0; nn < 8; nn++) {
            int c = nn * 8 + t2;
            *(float2*)(g_fjt + (row0 + g) * Dm + c)      = make_float2(C0[nn].x, C0[nn].y);
            *(float2*)(g_fjt + (row0 + 8 + g) * Dm + c)  = make_float2(C0[nn].z, C0[nn].w);
            *(float2*)(g_fjt + (row0 + 16 + g) * Dm + c) = make_float2(C1[nn].x, C1[nn].y);
            *(float2*)(g_fjt + (row0 + 24 + g) * Dm + c) = make_float2(C1[nn].z, C1[nn].w);
        }

        // ---- qj row pointers (<=2 distinct b per 32-row unit)
        int b0 = row0 / Ln;
        int rof = row0 - b0 * Ln;
        int nv0 = nodes_v[b0];
        int nv1 = nodes_v[(b0 + 1 < Bsz) ? b0 + 1 : Bsz - 1];
        const float* ei0 = embed_i + (size_t)((rof + g      >= Ln) ? nv1 : nv0) * 64;
        const float* ei1 = embed_i + (size_t)((rof + 8 + g  >= Ln) ? nv1 : nv0) * 64;
        const float* ei2 = embed_i + (size_t)((rof + 16 + g >= Ln) ? nv1 : nv0) * 64;
        const float* ei3 = embed_i + (size_t)((rof + 24 + g >= Ln) ? nv1 : nv0) * 64;

        // ---- at1: k 0..3 from fjt frags, k 4..7 from qj (JIT loads)
#pragma unroll
        for (int nn = 0; nn < 8; nn++) {
            D0[nn] = make_float4(0.f, 0.f, 0.f, 0.f);
            D1[nn] = make_float4(0.f, 0.f, 0.f, 0.f);
        }
#pragma unroll
        for (int kk = 0; kk < 4; kk++) {
            uint32_t ahA[4], alA[4], ahB[4], alB[4];
            afrag_fromC(C0[2 * kk], C0[2 * kk + 1], ahA, alA);
            afrag_fromC(C1[2 * kk], C1[2 * kk + 1], ahB, alB);
            const uint4* wk = WF + U_AT1 + kk * 256 + lane;
#pragma unroll
            for (int nn = 0; nn < 8; nn++) {
                uint4 w = wk[nn * 32];
                mma3(D0[nn], ahA, alA, w);
                mma3(D1[nn], ahB, alB, w);
            }
        }
#pragma unroll
        for (int kk = 0; kk < 4; kk++) {
            int c = kk * 16 + t2;
            float2 xa0 = *(const float2*)(ei0 + c);
            float2 xa1 = *(const float2*)(ei1 + c);
            float2 xa2 = *(const float2*)(ei0 + c + 8);
            float2 xa3 = *(const float2*)(ei1 + c + 8);
            float2 xb0 = *(const float2*)(ei2 + c);
            float2 xb1 = *(const float2*)(ei3 + c);
            float2 xb2 = *(const float2*)(ei2 + c + 8);
            float2 xb3 = *(const float2*)(ei3 + c + 8);
            uint32_t ahA[4], alA[4], ahB[4], alB[4];
            split2(xa0.x, xa0.y, ahA[0], alA[0]);
            split2(xa1.x, xa1.y, ahA[1], alA[1]);
            split2(xa2.x, xa2.y, ahA[2], alA[2]);
            split2(xa3.x, xa3.y, ahA[3], alA[3]);
            split2(xb0.x, xb0.y, ahB[0], alB[0]);
            split2(xb1.x, xb1.y, ahB[1], alB[1]);
            split2(xb2.x, xb2.y, ahB[2], alB[2]);
            split2(xb3.x, xb3.y, ahB[3], alB[3]);
            const uint4* wk = WF + U_AT1 + (kk + 4) * 256 + lane;
#pragma unroll
            for (int nn = 0; nn < 8; nn++) {
                uint4 w = wk[nn * 32];
                mma3(D0[nn], ahA, alA, w);
                mma3(D1[nn], ahB, alB, w);
            }
        }
        bias_act(D0, (const float2*)(sm + F_BA1), t, true);
        bias_act(D1, (const float2*)(sm + F_BA1), t, true);

#pragma unroll
        for (int nn = 0; nn < 8; nn++) {
            C0[nn] = make_float4(0.f, 0.f, 0.f, 0.f);
            C1[nn] = make_float4(0.f, 0.f, 0.f, 0.f);
        }
        gemm2_fromC(D0, D1, WF + U_AT2, lane, C0, C1);
        bias_act(C0, (const float2*)(sm + F_BA2), t, true);
        bias_act(C1, (const float2*)(sm + F_BA2), t, true);

        // ---- scores
        const float2* w32 = (const float2*)(sm + F_W3);
        float sA0 = 0.f, sA1 = 0.f, sB0 = 0.f, sB1 = 0.f;
#pragma unroll
        for (int nn = 0; nn < 8; nn++) {
            float2 w = w32[nn * 4 + t];
            sA0 += C0[nn].x * w.x + C0[nn].y * w.y;
            sA1 += C0[nn].z * w.x + C0[nn].w * w.y;
            sB0 += C1[nn].x * w.x + C1[nn].y * w.y;
            sB1 += C1[nn].z * w.x + C1[nn].w * w.y;
        }
        sA0 += __shfl_xor_sync(FULLMASK, sA0, 1); sA0 += __shfl_xor_sync(FULLMASK, sA0, 2);
        sA1 += __shfl_xor_sync(FULLMASK, sA1, 1); sA1 += __shfl_xor_sync(FULLMASK, sA1, 2);
        sB0 += __shfl_xor_sync(FULLMASK, sB0, 1); sB0 += __shfl_xor_sync(FULLMASK, sB0, 2);
        sB1 += __shfl_xor_sync(FULLMASK, sB1, 1); sB1 += __shfl_xor_sync(FULLMASK, sB1, 2);
        if (t == 0) {
            g_scores[row0 + g]      = sA0 + b3;
            g_scores[row0 + 8 + g]  = sA1 + b3;
            g_scores[row0 + 16 + g] = sB0 + b3;
            g_scores[row0 + 24 + g] = sB1 + b3;
        }
    }
}

// ---------------- K2: softmax + aggregation + combine MLP -------------------
__device__ __forceinline__ float wredmax(float v) {
#pragma unroll
    for (int o = 16; o; o >>= 1) v = fmaxf(v, __shfl_xor_sync(FULLMASK, v, o));
    return v;
}
__device__ __forceinline__ float wredsum(float v) {
#pragma unroll
    for (int o = 16; o; o >>= 1) v += __shfl_xor_sync(FULLMASK, v, o);
    return v;
}
constexpr int OFF_W1  = 0;
constexpr int OFF_W2  = 8192;
constexpr int OFF_B1  = 12288;
constexpr int OFF_B2  = 12352;
constexpr int OFF_XB2 = 12416;
constexpr int OFF_MU  = 12416 + 8 * 128;
constexpr int SMEM2_FLOATS = OFF_MU + 8 * 64;

template <int K, bool RELU>
__device__ __forceinline__ void mlp1(const float* __restrict__ W,
                                     const float* __restrict__ bias,
                                     const float* __restrict__ xb, int lane,
                                     float& o0, float& o1) {
    float c0 = 0.f, c1 = 0.f;
#pragma unroll 8
    for (int k = 0; k < K; k++) {
        float x = xb[k];
        c0 = fmaf(x, W[k * Dm + lane], c0);
        c1 = fmaf(x, W[k * Dm + lane + 32], c1);
    }
    c0 += bias[lane]; c1 += bias[lane + 32];
    if (RELU) { c0 = fmaxf(c0, 0.f); c1 = fmaxf(c1, 0.f); }
    o0 = c0; o1 = c1;
}

__global__ __launch_bounds__(256, 1)
void k_agg(const int* __restrict__ nodes_v, const float* __restrict__ embed_i,
           const float* __restrict__ w1, const float* __restrict__ b1,
           const float* __restrict__ w2, const float* __restrict__ b2,
           float* __restrict__ out) {
    extern __shared__ float smf[];
    cpf(smf + OFF_W1, w1, 8192);
    cpf(smf + OFF_W2, w2, 4096);
    cpf(smf + OFF_B1, b1, 64);
    cpf(smf + OFF_B2, b2, 64);
    __syncthreads();

    const int wid  = threadIdx.x >> 5;
    const int lane = threadIdx.x & 31;
    const int nw   = blockDim.x >> 5;
    float* xb = smf + OFF_XB2 + wid * 128;
    float* mu = smf + OFF_MU  + wid * 64;

    for (int b = blockIdx.x * nw + wid; b < Bsz; b += gridDim.x * nw) {
        const float* sc = g_scores + b * Ln;
        float s0 = (lane < Ln)        ? sc[lane]      : -1e30f;
        float s1 = ((lane + 32) < Ln) ? sc[lane + 32] : -1e30f;
        float m  = wredmax(fmaxf(s0, s1));
        float e0 = (lane < Ln)        ? expf(s0 - m) : 0.f;
        float e1 = ((lane + 32) < Ln) ? expf(s1 - m) : 0.f;
        float inv = 1.f / wredsum(e0 + e1);
        mu[lane]      = e0 * inv;
        mu[lane + 32] = e1 * inv;
        __syncwarp();

        // zj: lane owns d = 2*lane, 2*lane+1; fully unrolled, 1 LDG.64 per l
        float ax = 0.f, ay = 0.f;
        const float2* fj2 = (const float2*)(g_fjt + (size_t)b * Ln * Dm);
#pragma unroll
        for (int l = 0; l < Ln; l++) {
            float mm = mu[l];
            float2 v = fj2[l * 32 + lane];
            ax = fmaf(mm, v.x, ax);
            ay = fmaf(mm, v.y, ay);
        }
        ((float2*)xb)[lane] = make_float2(ax, ay);
        int iv = nodes_v[b];
        ((float2*)(xb + 64))[lane] = ((const float2*)embed_i)[iv * 32 + lane];
        __syncwarp();

        float z0, z1;
        mlp1<128, true>(smf + OFF_W1, smf + OFF_B1, xb, lane, z0, z1);
        __syncwarp();
        xb[lane]      = z0;
        xb[lane + 32] = z1;
        __syncwarp();
        float o0, o1;
        mlp1<64, true>(smf + OFF_W2, smf + OFF_B2, xb, lane, o0, o1);
        out[b * Dm + lane]      = o0;
        out[b * Dm + lane + 32] = o1;
        __syncwarp();
    }
}

// ---------------- launch ----------------------------------------------------
extern "C" void kernel_launch(void* const* d_in, const int* in_sizes, int n_in,
                              void* d_out, int out_size) {
    const int*   nodes_v = (const int*)d_in[0];
    const int*   neigh_u = (const int*)d_in[1];
    const int*   neigh_r = (const int*)d_in[2];
    const float* embed_u = (const float*)d_in[3];
    const float* embed_i = (const float*)d_in[4];
    const float* embed_r = (const float*)d_in[5];
    const float* gv_w1 = (const float*)d_in[6];
    const float* gv_b1 = (const float*)d_in[7];
    const float* gv_w2 = (const float*)d_in[8];
    const float* gv_b2 = (const float*)d_in[9];
    const float* gv_w3 = (const float*)d_in[10];
    const float* gv_b3 = (const float*)d_in[11];
    const float* at_w1 = (const float*)d_in[12];
    const float* at_b1 = (const float*)d_in[13];
    const float* at_w2 = (const float*)d_in[14];
    const float* at_b2 = (const float*)d_in[15];
    const float* at_w3 = (const float*)d_in[16];
    const float* at_b3 = (const float*)d_in[17];
    const float* wr1_w = (const float*)d_in[18];
    const float* wr1_b = (const float*)d_in[19];
    const float* wr2_w = (const float*)d_in[20];
    const float* wr2_b = (const float*)d_in[21];
    float* out = (float*)d_out;

    int nsm = 148;
    cudaDeviceGetAttribute(&nsm, cudaDevAttrMultiProcessorCount, 0);

    const size_t s1 = SMEM1_FLOATS * sizeof(float);
    const size_t s2 = SMEM2_FLOATS * sizeof(float);
    cudaFuncSetAttribute(k_rows, cudaFuncAttributeMaxDynamicSharedMemorySize, (int)s1);
    cudaFuncSetAttribute(k_agg,  cudaFuncAttributeMaxDynamicSharedMemorySize, (int)s2);

    k_rows<<<nsm, 32 * WARPS, s1>>>(nodes_v, neigh_u, neigh_r,
                                    embed_u, embed_i, embed_r,
                                    gv_w1, gv_b1, gv_w2, gv_b2, gv_w3, gv_b3,
                                    at_w1, at_b1, at_w2, at_b2, at_w3, at_b3);
    k_agg<<<512, 256, s2>>>(nodes_v, embed_i, wr1_w, wr1_b, wr2_w, wr2_b, out);
}

// round 8
// speedup vs baseline: 5.4130x; 1.2778x over previous
#include <cuda_runtime.h>
#include <cuda_fp16.h>
#include <cstdint>

#define FULLMASK 0xffffffffu

constexpr int Bsz  = 4096;
constexpr int Ln   = 50;
constexpr int Dm   = 64;
constexpr int ROWS = Bsz * Ln;       // 204800
constexpr int NUNIT = ROWS / 32;     // 6400 32-row units
constexpr int WARPS = 12;

// ---------------- scratch ---------------------------------------------------
__device__ float g_fjt[ROWS * Dm];
__device__ float g_scores[ROWS];

// ---------------- smem float offsets (k_rows) -------------------------------
constexpr int F_WF  = 0;                  // 28672 floats (7168 uint4)
constexpr int F_ERT = 28672;              // embed_r fp16 LUT (80 uint2 = 160 floats)
constexpr int F_B1  = 28992;
constexpr int F_B2  = 29056;
constexpr int F_B3  = 29120;
constexpr int F_BA1 = 29184;
constexpr int F_BA2 = 29248;
constexpr int F_W3  = 29312;
constexpr int F_B3S = 29376;
constexpr int SMEM1_FLOATS = 29380;
constexpr int U_GV1 = 0, U_GV2 = 2048, U_GV3 = 3072, U_AT1 = 4096, U_AT2 = 6144;

// ---------------- helpers ---------------------------------------------------
__device__ __forceinline__ void cpf(float* dst, const float* __restrict__ src, int n) {
    for (int i = threadIdx.x; i < n; i += blockDim.x) dst[i] = src[i];
}
// pack {lo: f16(x0), hi: f16(x1)}
__device__ __forceinline__ uint32_t hpack(float x0, float x1) {
    uint32_t r;
    asm("cvt.rn.f16x2.f32 %0, %1, %2;" : "=r"(r) : "f"(x1), "f"(x0));
    return r;
}
// exact fp16 split of a pair
__device__ __forceinline__ void hsplit(float x0, float x1, uint32_t& hi, uint32_t& lo) {
    hi = hpack(x0, x1);
    __half2 h = *reinterpret_cast<__half2*>(&hi);
    float2 f = __half22float2(h);
    lo = hpack(x0 - f.x, x1 - f.y);
}
__device__ __forceinline__ void mma16816(float4& c, const uint32_t a[4],
                                         uint32_t b0, uint32_t b1) {
    asm volatile(
        "mma.sync.aligned.m16n8k16.row.col.f32.f16.f16.f32 "
        "{%0,%1,%2,%3}, {%4,%5,%6,%7}, {%8,%9}, {%0,%1,%2,%3};\n"
        : "+f"(c.x), "+f"(c.y), "+f"(c.z), "+f"(c.w)
        : "r"(a[0]), "r"(a[1]), "r"(a[2]), "r"(a[3]), "r"(b0), "r"(b1));
}
// 2-term: C += A*Whi + A*Wlo  (w = {hi01, hi89, lo01, lo89})
__device__ __forceinline__ void mma2(float4& c, const uint32_t ah[4], uint4 w) {
    mma16816(c, ah, w.x, w.y);
    mma16816(c, ah, w.z, w.w);
}

// weights [K x 64] -> B-fragment order {hi01, hi89, lo01, lo89} (fp16 split)
__device__ void stage_w(uint4* dst, const float* __restrict__ W, int KSTEPS) {
    int total = KSTEPS * 256;
    for (int i = threadIdx.x; i < total; i += blockDim.x) {
        int kk = i >> 8, rem = i & 255, nn = rem >> 5, lane = rem & 31;
        int g = lane >> 2, t2 = (lane & 3) * 2;
        int col = nn * 8 + g;
        int k0 = kk * 16 + t2;
        uint4 e;
        hsplit(W[k0 * 64 + col], W[(k0 + 1) * 64 + col], e.x, e.z);
        hsplit(W[(k0 + 8) * 64 + col], W[(k0 + 9) * 64 + col], e.y, e.w);
        dst[i] = e;
    }
}

__device__ __forceinline__ void bias_act(float4 C[8], const float2* __restrict__ b2,
                                         int t, bool relu) {
#pragma unroll
    for (int nn = 0; nn < 8; nn++) {
        float2 b = b2[nn * 4 + t];
        C[nn].x += b.x; C[nn].y += b.y; C[nn].z += b.x; C[nn].w += b.y;
        if (relu) {
            C[nn].x = fmaxf(C[nn].x, 0.f); C[nn].y = fmaxf(C[nn].y, 0.f);
            C[nn].z = fmaxf(C[nn].z, 0.f); C[nn].w = fmaxf(C[nn].w, 0.f);
        }
    }
}

__device__ __forceinline__ void afrag_fromC(const float4& u, const float4& v,
                                            uint32_t ah[4]) {
    ah[0] = hpack(u.x, u.y);
    ah[1] = hpack(u.z, u.w);
    ah[2] = hpack(v.x, v.y);
    ah[3] = hpack(v.z, v.w);
}

// dual-half fromC GEMM (K=64): halves share each weight fragment read
__device__ __forceinline__ void gemm2_fromC(const float4 P0[8], const float4 P1[8],
                                            const uint4* __restrict__ WK, int lane,
                                            float4 C0[8], float4 C1[8]) {
#pragma unroll
    for (int kk = 0; kk < 4; kk++) {
        uint32_t ahA[4], ahB[4];
        afrag_fromC(P0[2 * kk], P0[2 * kk + 1], ahA);
        afrag_fromC(P1[2 * kk], P1[2 * kk + 1], ahB);
        const uint4* wk = WK + kk * 256 + lane;
#pragma unroll
        for (int nn = 0; nn < 8; nn++) {
            uint4 w = wk[nn * 32];
            mma2(C0[nn], ahA, w);
            mma2(C1[nn], ahB, w);
        }
    }
}

// ---------------- K1: fused row MLPs, M=32/warp, fp16 2-term ----------------
__global__ __launch_bounds__(32 * WARPS, 1)
void k_rows(const int* __restrict__ nodes_v, const int* __restrict__ neigh_u,
            const int* __restrict__ neigh_r,
            const float* __restrict__ embed_u, const float* __restrict__ embed_i,
            const float* __restrict__ embed_r,
            const float* __restrict__ gw1, const float* __restrict__ gb1,
            const float* __restrict__ gw2, const float* __restrict__ gb2,
            const float* __restrict__ gw3, const float* __restrict__ gb3,
            const float* __restrict__ aw1, const float* __restrict__ ab1,
            const float* __restrict__ aw2, const float* __restrict__ ab2,
            const float* __restrict__ aw3, const float* __restrict__ ab3) {
    extern __shared__ float sm[];
    uint4* WF = reinterpret_cast<uint4*>(sm + F_WF);
    uint2* ERT = reinterpret_cast<uint2*>(sm + F_ERT);
    stage_w(WF + U_GV1, gw1, 8);
    stage_w(WF + U_GV2, gw2, 4);
    stage_w(WF + U_GV3, gw3, 4);
    stage_w(WF + U_AT1, aw1, 8);
    stage_w(WF + U_AT2, aw2, 4);
    // embed_r activation LUT (single fp16): [rr][kk][t] -> {a01, a89}
    for (int i = threadIdx.x; i < 80; i += blockDim.x) {
        int rr = i >> 4, kk = (i >> 2) & 3, t = i & 3;
        int c = kk * 16 + t * 2;
        const float* er = embed_r + rr * 64;
        uint2 e;
        e.x = hpack(er[c], er[c + 1]);
        e.y = hpack(er[c + 8], er[c + 9]);
        ERT[i] = e;
    }
    cpf(sm + F_B1,  gb1, 64);
    cpf(sm + F_B2,  gb2, 64);
    cpf(sm + F_B3,  gb3, 64);
    cpf(sm + F_BA1, ab1, 64);
    cpf(sm + F_BA2, ab2, 64);
    cpf(sm + F_W3,  aw3, 64);
    if (threadIdx.x == 0) sm[F_B3S] = ab3[0];
    __syncthreads();

    const int wid  = threadIdx.x >> 5;
    const int lane = threadIdx.x & 31;
    const int g    = lane >> 2;
    const int t    = lane & 3;
    const int t2   = t * 2;
    const float b3 = sm[F_B3S];

    const int wg      = blockIdx.x * WARPS + wid;
    const int wstride = gridDim.x * WARPS;

    for (int unit = wg; unit < NUNIT; unit += wstride) {
        const int row0 = unit * 32;
        int u0 = neigh_u[row0 + g],      u1 = neigh_u[row0 + 8 + g];
        int u2 = neigh_u[row0 + 16 + g], u3 = neigh_u[row0 + 24 + g];
        int r0i = neigh_r[row0 + g],      r1i = neigh_r[row0 + 8 + g];
        int r2i = neigh_r[row0 + 16 + g], r3i = neigh_r[row0 + 24 + g];
        const float* eu0 = embed_u + (size_t)u0 * 64;
        const float* eu1 = embed_u + (size_t)u1 * 64;
        const float* eu2 = embed_u + (size_t)u2 * 64;
        const float* eu3 = embed_u + (size_t)u3 * 64;

        float4 C0[8] = {}, C1[8] = {};
        // ---- gv1, k-steps 0..3 (pt, JIT global loads -> single fp16)
#pragma unroll
        for (int kk = 0; kk < 4; kk++) {
            int c = kk * 16 + t2;
            float2 a0 = *(const float2*)(eu0 + c);
            float2 a1 = *(const float2*)(eu1 + c);
            float2 a2 = *(const float2*)(eu0 + c + 8);
            float2 a3 = *(const float2*)(eu1 + c + 8);
            float2 b0 = *(const float2*)(eu2 + c);
            float2 b1 = *(const float2*)(eu3 + c);
            float2 b2 = *(const float2*)(eu2 + c + 8);
            float2 b3v = *(const float2*)(eu3 + c + 8);
            uint32_t ahA[4], ahB[4];
            ahA[0] = hpack(a0.x, a0.y); ahA[1] = hpack(a1.x, a1.y);
            ahA[2] = hpack(a2.x, a2.y); ahA[3] = hpack(a3.x, a3.y);
            ahB[0] = hpack(b0.x, b0.y); ahB[1] = hpack(b1.x, b1.y);
            ahB[2] = hpack(b2.x, b2.y); ahB[3] = hpack(b3v.x, b3v.y);
            const uint4* wk = WF + U_GV1 + kk * 256 + lane;
#pragma unroll
            for (int nn = 0; nn < 8; nn++) {
                uint4 w = wk[nn * 32];
                mma2(C0[nn], ahA, w);
                mma2(C1[nn], ahB, w);
            }
        }
        // ---- gv1, k-steps 4..7 (er from LUT)
#pragma unroll
        for (int kk = 0; kk < 4; kk++) {
            uint2 eA0 = ERT[(r0i * 4 + kk) * 4 + t];
            uint2 eA1 = ERT[(r1i * 4 + kk) * 4 + t];
            uint2 eB0 = ERT[(r2i * 4 + kk) * 4 + t];
            uint2 eB1 = ERT[(r3i * 4 + kk) * 4 + t];
            uint32_t ahA[4] = {eA0.x, eA1.x, eA0.y, eA1.y};
            uint32_t ahB[4] = {eB0.x, eB1.x, eB0.y, eB1.y};
            const uint4* wk = WF + U_GV1 + (kk + 4) * 256 + lane;
#pragma unroll
            for (int nn = 0; nn < 8; nn++) {
                uint4 w = wk[nn * 32];
                mma2(C0[nn], ahA, w);
                mma2(C1[nn], ahB, w);
            }
        }
        bias_act(C0, (const float2*)(sm + F_B1), t, true);
        bias_act(C1, (const float2*)(sm + F_B1), t, true);

        float4 D0[8] = {}, D1[8] = {};
        gemm2_fromC(C0, C1, WF + U_GV2, lane, D0, D1);
        bias_act(D0, (const float2*)(sm + F_B2), t, true);
        bias_act(D1, (const float2*)(sm + F_B2), t, true);

#pragma unroll
        for (int nn = 0; nn < 8; nn++) {
            C0[nn] = make_float4(0.f, 0.f, 0.f, 0.f);
            C1[nn] = make_float4(0.f, 0.f, 0.f, 0.f);
        }
        gemm2_fromC(D0, D1, WF + U_GV3, lane, C0, C1);
        bias_act(C0, (const float2*)(sm + F_B3), t, false);
        bias_act(C1, (const float2*)(sm + F_B3), t, false);   // C = fjt frags

        // ---- fjt -> global
#pragma unroll
        for (int nn = 0; nn < 8; nn++) {
            int c = nn * 8 + t2;
            *(float2*)(g_fjt + (row0 + g) * Dm + c)      = make_float2(C0[nn].x, C0[nn].y);
            *(float2*)(g_fjt + (row0 + 8 + g) * Dm + c)  = make_float2(C0[nn].z, C0[nn].w);
            *(float2*)(g_fjt + (row0 + 16 + g) * Dm + c) = make_float2(C1[nn].x, C1[nn].y);
            *(float2*)(g_fjt + (row0 + 24 + g) * Dm + c) = make_float2(C1[nn].z, C1[nn].w);
        }

        // ---- qj row pointers (<=2 distinct b per 32-row unit)
        int b0i = row0 / Ln;
        int rof = row0 - b0i * Ln;
        int nv0 = nodes_v[b0i];
        int nv1 = nodes_v[(b0i + 1 < Bsz) ? b0i + 1 : Bsz - 1];
        const float* ei0 = embed_i + (size_t)((rof + g      >= Ln) ? nv1 : nv0) * 64;
        const float* ei1 = embed_i + (size_t)((rof + 8 + g  >= Ln) ? nv1 : nv0) * 64;
        const float* ei2 = embed_i + (size_t)((rof + 16 + g >= Ln) ? nv1 : nv0) * 64;
        const float* ei3 = embed_i + (size_t)((rof + 24 + g >= Ln) ? nv1 : nv0) * 64;

        // ---- at1: k 0..3 from fjt frags, k 4..7 from qj
#pragma unroll
        for (int nn = 0; nn < 8; nn++) {
            D0[nn] = make_float4(0.f, 0.f, 0.f, 0.f);
            D1[nn] = make_float4(0.f, 0.f, 0.f, 0.f);
        }
#pragma unroll
        for (int kk = 0; kk < 4; kk++) {
            uint32_t ahA[4], ahB[4];
            afrag_fromC(C0[2 * kk], C0[2 * kk + 1], ahA);
            afrag_fromC(C1[2 * kk], C1[2 * kk + 1], ahB);
            const uint4* wk = WF + U_AT1 + kk * 256 + lane;
#pragma unroll
            for (int nn = 0; nn < 8; nn++) {
                uint4 w = wk[nn * 32];
                mma2(D0[nn], ahA, w);
                mma2(D1[nn], ahB, w);
            }
        }
#pragma unroll
        for (int kk = 0; kk < 4; kk++) {
            int c = kk * 16 + t2;
            float2 xa0 = *(const float2*)(ei0 + c);
            float2 xa1 = *(const float2*)(ei1 + c);
            float2 xa2 = *(const float2*)(ei0 + c + 8);
            float2 xa3 = *(const float2*)(ei1 + c + 8);
            float2 xb0 = *(const float2*)(ei2 + c);
            float2 xb1 = *(const float2*)(ei3 + c);
            float2 xb2 = *(const float2*)(ei2 + c + 8);
            float2 xb3 = *(const float2*)(ei3 + c + 8);
            uint32_t ahA[4], ahB[4];
            ahA[0] = hpack(xa0.x, xa0.y); ahA[1] = hpack(xa1.x, xa1.y);
            ahA[2] = hpack(xa2.x, xa2.y); ahA[3] = hpack(xa3.x, xa3.y);
            ahB[0] = hpack(xb0.x, xb0.y); ahB[1] = hpack(xb1.x, xb1.y);
            ahB[2] = hpack(xb2.x, xb2.y); ahB[3] = hpack(xb3.x, xb3.y);
            const uint4* wk = WF + U_AT1 + (kk + 4) * 256 + lane;
#pragma unroll
            for (int nn = 0; nn < 8; nn++) {
                uint4 w = wk[nn * 32];
                mma2(D0[nn], ahA, w);
                mma2(D1[nn], ahB, w);
            }
        }
        bias_act(D0, (const float2*)(sm + F_BA1), t, true);
        bias_act(D1, (const float2*)(sm + F_BA1), t, true);

#pragma unroll
        for (int nn = 0; nn < 8; nn++) {
            C0[nn] = make_float4(0.f, 0.f, 0.f, 0.f);
            C1[nn] = make_float4(0.f, 0.f, 0.f, 0.f);
        }
        gemm2_fromC(D0, D1, WF + U_AT2, lane, C0, C1);
        bias_act(C0, (const float2*)(sm + F_BA2), t, true);
        bias_act(C1, (const float2*)(sm + F_BA2), t, true);

        // ---- scores
        const float2* w32 = (const float2*)(sm + F_W3);
        float sA0 = 0.f, sA1 = 0.f, sB0 = 0.f, sB1 = 0.f;
#pragma unroll
        for (int nn = 0; nn < 8; nn++) {
            float2 w = w32[nn * 4 + t];
            sA0 += C0[nn].x * w.x + C0[nn].y * w.y;
            sA1 += C0[nn].z * w.x + C0[nn].w * w.y;
            sB0 += C1[nn].x * w.x + C1[nn].y * w.y;
            sB1 += C1[nn].z * w.x + C1[nn].w * w.y;
        }
        sA0 += __shfl_xor_sync(FULLMASK, sA0, 1); sA0 += __shfl_xor_sync(FULLMASK, sA0, 2);
        sA1 += __shfl_xor_sync(FULLMASK, sA1, 1); sA1 += __shfl_xor_sync(FULLMASK, sA1, 2);
        sB0 += __shfl_xor_sync(FULLMASK, sB0, 1); sB0 += __shfl_xor_sync(FULLMASK, sB0, 2);
        sB1 += __shfl_xor_sync(FULLMASK, sB1, 1); sB1 += __shfl_xor_sync(FULLMASK, sB1, 2);
        if (t == 0) {
            g_scores[row0 + g]      = sA0 + b3;
            g_scores[row0 + 8 + g]  = sA1 + b3;
            g_scores[row0 + 16 + g] = sB0 + b3;
            g_scores[row0 + 24 + g] = sB1 + b3;
        }
    }
}

// ---------------- K2: softmax + aggregation + combine MLP -------------------
__device__ __forceinline__ float wredmax(float v) {
#pragma unroll
    for (int o = 16; o; o >>= 1) v = fmaxf(v, __shfl_xor_sync(FULLMASK, v, o));
    return v;
}
__device__ __forceinline__ float wredsum(float v) {
#pragma unroll
    for (int o = 16; o; o >>= 1) v += __shfl_xor_sync(FULLMASK, v, o);
    return v;
}
constexpr int AGG_WARPS = 16;
constexpr int OFF_W1  = 0;
constexpr int OFF_W2  = 8192;
constexpr int OFF_B1  = 12288;
constexpr int OFF_B2  = 12352;
constexpr int OFF_XB2 = 12416;                         // 16 warps * 128
constexpr int OFF_MU  = OFF_XB2 + AGG_WARPS * 128;     // 16 warps * 64
constexpr int SMEM2_FLOATS = OFF_MU + AGG_WARPS * 64;

template <int K, bool RELU>
__device__ __forceinline__ void mlp1(const float* __restrict__ W,
                                     const float* __restrict__ bias,
                                     const float* __restrict__ xb, int lane,
                                     float& o0, float& o1) {
    float c0 = 0.f, c1 = 0.f;
#pragma unroll 8
    for (int k = 0; k < K; k++) {
        float x = xb[k];
        c0 = fmaf(x, W[k * Dm + lane], c0);
        c1 = fmaf(x, W[k * Dm + lane + 32], c1);
    }
    c0 += bias[lane]; c1 += bias[lane + 32];
    if (RELU) { c0 = fmaxf(c0, 0.f); c1 = fmaxf(c1, 0.f); }
    o0 = c0; o1 = c1;
}

__global__ __launch_bounds__(32 * AGG_WARPS, 1)
void k_agg(const int* __restrict__ nodes_v, const float* __restrict__ embed_i,
           const float* __restrict__ w1, const float* __restrict__ b1,
           const float* __restrict__ w2, const float* __restrict__ b2,
           float* __restrict__ out) {
    extern __shared__ float smf[];
    cpf(smf + OFF_W1, w1, 8192);
    cpf(smf + OFF_W2, w2, 4096);
    cpf(smf + OFF_B1, b1, 64);
    cpf(smf + OFF_B2, b2, 64);
    __syncthreads();

    const int wid  = threadIdx.x >> 5;
    const int lane = threadIdx.x & 31;
    float* xb = smf + OFF_XB2 + wid * 128;
    float* mu = smf + OFF_MU  + wid * 64;

    for (int b = blockIdx.x * AGG_WARPS + wid; b < Bsz; b += gridDim.x * AGG_WARPS) {
        const float* sc = g_scores + b * Ln;
        float s0 = (lane < Ln)        ? sc[lane]      : -1e30f;
        float s1 = ((lane + 32) < Ln) ? sc[lane + 32] : -1e30f;
        float m  = wredmax(fmaxf(s0, s1));
        float e0 = (lane < Ln)        ? expf(s0 - m) : 0.f;
        float e1 = ((lane + 32) < Ln) ? expf(s1 - m) : 0.f;
        float inv = 1.f / wredsum(e0 + e1);
        mu[lane]      = e0 * inv;
        mu[lane + 32] = e1 * inv;
        __syncwarp();

        float ax = 0.f, ay = 0.f;
        const float2* fj2 = (const float2*)(g_fjt + (size_t)b * Ln * Dm);
#pragma unroll 10
        for (int l = 0; l < Ln; l++) {
            float mm = mu[l];
            float2 v = fj2[l * 32 + lane];
            ax = fmaf(mm, v.x, ax);
            ay = fmaf(mm, v.y, ay);
        }
        ((float2*)xb)[lane] = make_float2(ax, ay);
        int iv = nodes_v[b];
        ((float2*)(xb + 64))[lane] = ((const float2*)embed_i)[iv * 32 + lane];
        __syncwarp();

        float z0, z1;
        mlp1<128, true>(smf + OFF_W1, smf + OFF_B1, xb, lane, z0, z1);
        __syncwarp();
        xb[lane]      = z0;
        xb[lane + 32] = z1;
        __syncwarp();
        float o0, o1;
        mlp1<64, true>(smf + OFF_W2, smf + OFF_B2, xb, lane, o0, o1);
        out[b * Dm + lane]      = o0;
        out[b * Dm + lane + 32] = o1;
        __syncwarp();
    }
}

// ---------------- launch ----------------------------------------------------
extern "C" void kernel_launch(void* const* d_in, const int* in_sizes, int n_in,
                              void* d_out, int out_size) {
    const int*   nodes_v = (const int*)d_in[0];
    const int*   neigh_u = (const int*)d_in[1];
    const int*   neigh_r = (const int*)d_in[2];
    const float* embed_u = (const float*)d_in[3];
    const float* embed_i = (const float*)d_in[4];
    const float* embed_r = (const float*)d_in[5];
    const float* gv_w1 = (const float*)d_in[6];
    const float* gv_b1 = (const float*)d_in[7];
    const float* gv_w2 = (const float*)d_in[8];
    const float* gv_b2 = (const float*)d_in[9];
    const float* gv_w3 = (const float*)d_in[10];
    const float* gv_b3 = (const float*)d_in[11];
    const float* at_w1 = (const float*)d_in[12];
    const float* at_b1 = (const float*)d_in[13];
    const float* at_w2 = (const float*)d_in[14];
    const float* at_b2 = (const float*)d_in[15];
    const float* at_w3 = (const float*)d_in[16];
    const float* at_b3 = (const float*)d_in[17];
    const float* wr1_w = (const float*)d_in[18];
    const float* wr1_b = (const float*)d_in[19];
    const float* wr2_w = (const float*)d_in[20];
    const float* wr2_b = (const float*)d_in[21];
    float* out = (float*)d_out;

    int nsm = 148;
    cudaDeviceGetAttribute(&nsm, cudaDevAttrMultiProcessorCount, 0);

    const size_t s1 = SMEM1_FLOATS * sizeof(float);
    const size_t s2 = SMEM2_FLOATS * sizeof(float);
    cudaFuncSetAttribute(k_rows, cudaFuncAttributeMaxDynamicSharedMemorySize, (int)s1);
    cudaFuncSetAttribute(k_agg,  cudaFuncAttributeMaxDynamicSharedMemorySize, (int)s2);

    k_rows<<<nsm, 32 * WARPS, s1>>>(nodes_v, neigh_u, neigh_r,
                                    embed_u, embed_i, embed_r,
                                    gv_w1, gv_b1, gv_w2, gv_b2, gv_w3, gv_b3,
                                    at_w1, at_b1, at_w2, at_b2, at_w3, at_b3);
    k_agg<<<nsm, 32 * AGG_WARPS, s2>>>(nodes_v, embed_i, wr1_w, wr1_b, wr2_w, wr2_b, out);
}